// round 14
// baseline (speedup 1.0000x reference)
#include <cuda_runtime.h>
#include <cuda_fp16.h>
#include <mma.h>
#include <math.h>

using namespace nvcuda;

#define NN    8192
#define DIN   128
#define HDIM  256
#define NWORD 256               // 8192/32 mask words per row
#define NTILE 64                // 8192/128 tile grid
#define NUT   2080              // upper-triangle tile count (64*65/2)
#define KRANK 63753420u         // nearest-rank index of 0.95 quantile over N*N values
#define CAND_CAP (1u << 24)     // 16M candidate slots (64 MB)
#define AGG_BM 64               // dst rows per wmma-agg block
#define AGG_KC 64               // k-chunk (src rows staged in smem)

typedef unsigned long long u64;

// packed f32x2 helpers (sm_103a): 2 independent fp32 FMAs per instruction, bit-identical
#define FMA2(d, a, b)   asm("fma.rn.f32x2 %0, %1, %2, %0;" : "+l"(d) : "l"(a), "l"(b))
#define DUP2(d, s)      asm("mov.b64 %0, {%1, %1};" : "=l"(d) : "f"(s))
#define UNPK(lo, hi, s) asm("mov.b64 {%0, %1}, %2;" : "=f"(lo), "=f"(hi) : "l"(s))

// ----------------- device scratch (static globals; no runtime allocation) -----------------
__device__ float    g_xn  [NN * DIN];          // normalized x            (4 MB)
__device__ float    g_sim [(size_t)NN * NN];   // |xn@xn^T|, UPPER TILES ONLY valid
__device__ unsigned g_adj [NN * NWORD];        // adjacency bitmask       (8 MB)
__device__ float    g_inv [NN];                // 1/deg
__device__ float    g_h0  [NN * HDIM];
__device__ float    g_h1  [NN * HDIM];
__device__ float    g_h2  [NN * HDIM];
__device__ __half   g_h0f [NN * HDIM];         // fp16 copy for aggregation
__device__ __half   g_h1f [NN * HDIM];
__device__ float    g_agg [NN * HDIM];
__device__ float    g_yl  [NN];
__device__ float    g_yr  [NN];
__device__ float    g_sc  [NN];
__device__ float    g_o1v [NN];
__device__ unsigned g_hist[8192];
__device__ unsigned g_cand[CAND_CAP];          // compacted pass-1 candidates
__device__ unsigned g_cnt;
__device__ unsigned g_key;
__device__ unsigned g_rem;

// decode linear upper-triangle tile index -> (bi, bj), bi <= bj
__device__ __forceinline__ void tile_decode(int tl, int& bi, int& bj) {
    int b = 0, rem = tl;
    while (rem >= NTILE - b) { rem -= NTILE - b; b++; }
    bi = b; bj = b + rem;
}

// ----------------- 1. row-normalize x (clamp norm at 1e-8) -----------------
__global__ void k_normalize(const float* __restrict__ x) {
    int row = blockIdx.x;
    int t   = threadIdx.x;                 // 128 threads = 1 col each
    float v = x[row * DIN + t];
    float s = v * v;
    #pragma unroll
    for (int o = 16; o; o >>= 1) s += __shfl_xor_sync(0xffffffffu, s, o);
    __shared__ float ws[4];
    if ((t & 31) == 0) ws[t >> 5] = s;
    __syncthreads();
    float nrm = fmaxf(sqrtf(ws[0] + ws[1] + ws[2] + ws[3]), 1e-8f);
    g_xn[row * DIN + t] = v / nrm;
}

// ----------------- 2. sim = |xn @ xn^T|, upper-triangle tiles ONLY, FFMA2 inner ---------
__global__ void __launch_bounds__(256, 2) k_simgemm_sym() {
    const int bi = blockIdx.x, bj = blockIdx.y;
    if (bj < bi) return;                       // only upper tiles computed & stored

    __shared__ float As[16][132];
    __shared__ float Bs[16][132];

    const int t  = threadIdx.x;
    const int tx = t & 15, ty = t >> 4;
    const int r0 = bi * 128, c0 = bj * 128;

    u64 acc2[8][4];                            // {acc[i][2j], acc[i][2j+1]} packed pairs
    #pragma unroll
    for (int i = 0; i < 8; i++)
        #pragma unroll
        for (int j = 0; j < 4; j++) acc2[i][j] = 0ull;

    for (int k0 = 0; k0 < DIN; k0 += 16) {
        #pragma unroll
        for (int i = 0; i < 2; i++) {
            int lid = t + i * 256;              // 0..511
            int row = lid >> 2;                 // 0..127
            int q   = lid & 3;
            float4 a = *(const float4*)(g_xn + (size_t)(r0 + row) * DIN + k0 + q * 4);
            As[q*4+0][row] = a.x; As[q*4+1][row] = a.y;
            As[q*4+2][row] = a.z; As[q*4+3][row] = a.w;
            float4 b = *(const float4*)(g_xn + (size_t)(c0 + row) * DIN + k0 + q * 4);
            Bs[q*4+0][row] = b.x; Bs[q*4+1][row] = b.y;
            Bs[q*4+2][row] = b.z; Bs[q*4+3][row] = b.w;
        }
        __syncthreads();
        #pragma unroll
        for (int kk = 0; kk < 16; kk++) {
            float a[8];
            *(float4*)&a[0] = *(const float4*)&As[kk][ty * 4];
            *(float4*)&a[4] = *(const float4*)&As[kk][64 + ty * 4];
            u64 bv[4];
            {
                const u64* bp0 = (const u64*)&Bs[kk][tx * 4];
                const u64* bp1 = (const u64*)&Bs[kk][64 + tx * 4];
                bv[0] = bp0[0]; bv[1] = bp0[1];
                bv[2] = bp1[0]; bv[3] = bp1[1];
            }
            #pragma unroll
            for (int i = 0; i < 8; i++) {
                u64 a2; DUP2(a2, a[i]);
                FMA2(acc2[i][0], a2, bv[0]);
                FMA2(acc2[i][1], a2, bv[1]);
                FMA2(acc2[i][2], a2, bv[2]);
                FMA2(acc2[i][3], a2, bv[3]);
            }
        }
        __syncthreads();
    }
    #pragma unroll
    for (int i = 0; i < 8; i++) {
        int row = r0 + ((i >> 2) << 6) + ty * 4 + (i & 3);
        float* dst = g_sim + (size_t)row * NN + c0;
        float v[8];
        #pragma unroll
        for (int j = 0; j < 4; j++) UNPK(v[2*j], v[2*j+1], acc2[i][j]);
        *(float4*)(dst + tx * 4) =
            make_float4(fabsf(v[0]), fabsf(v[1]), fabsf(v[2]), fabsf(v[3]));
        *(float4*)(dst + 64 + tx * 4) =
            make_float4(fabsf(v[4]), fabsf(v[5]), fabsf(v[6]), fabsf(v[7]));
    }
}

// ----------------- 3. exact k-th order statistic: radix select over UPPER tiles ---------
__global__ void k_init_sel() {
    if (threadIdx.x == 0) { g_key = 0u; g_rem = KRANK; g_cnt = 0u; }
    for (int i = threadIdx.x; i < 8192; i += blockDim.x) g_hist[i] = 0u;
}

template <int PASS>
__global__ void k_hist() {
    __shared__ unsigned sh[8192];
    __shared__ unsigned buf[(PASS == 1) ? 4096 : 1];
    __shared__ unsigned bcnt, gbase;
    for (int i = threadIdx.x; i < 8192; i += blockDim.x) sh[i] = 0u;
    if (threadIdx.x == 0) bcnt = 0u;
    __syncthreads();
    const unsigned key = g_key;
    const unsigned kp1 = key >> 19;
    const int t = threadIdx.x;
    for (int tl = blockIdx.x; tl < NUT; tl += gridDim.x) {
        int bi, bj; tile_decode(tl, bi, bj);
        const unsigned wgt = (bi == bj) ? 1u : 2u;
        const size_t base = (size_t)bi * 128 * NN + bj * 128;
        #pragma unroll 4
        for (int i = 0; i < 16; i++) {
            int lin = i * 256 + t;
            int r = lin >> 5, c = lin & 31;
            float4 v = __ldg((const float4*)(g_sim + base + (size_t)r * NN) + c);
            float vv[4] = {v.x, v.y, v.z, v.w};
            #pragma unroll
            for (int u = 0; u < 4; u++) {
                unsigned b = __float_as_uint(vv[u]);
                if (PASS == 0) {
                    atomicAdd(&sh[b >> 19], wgt);
                } else {
                    if ((b >> 19) == kp1) {
                        atomicAdd(&sh[(b >> 6) & 8191u], wgt);
                        unsigned slot = atomicAdd(&bcnt, wgt);   // smem atomic, rare
                        buf[slot] = b;
                        if (wgt == 2u) buf[slot + 1] = b;
                    }
                }
            }
            if (PASS == 1) {
                __syncthreads();
                if (bcnt > 2048u) {              // flush: ONE global atomic per ~2K cands
                    if (t == 0) gbase = atomicAdd(&g_cnt, bcnt);
                    __syncthreads();
                    unsigned n = bcnt, gb = gbase;
                    for (unsigned j = t; j < n; j += 256)
                        if (gb + j < CAND_CAP) g_cand[gb + j] = buf[j];
                    __syncthreads();
                    if (t == 0) bcnt = 0u;
                    __syncthreads();
                }
            }
        }
    }
    if (PASS == 1) {                              // final flush
        __syncthreads();
        if (bcnt > 0u) {
            if (t == 0) gbase = atomicAdd(&g_cnt, bcnt);
            __syncthreads();
            unsigned n = bcnt, gb = gbase;
            for (unsigned j = t; j < n; j += 256)
                if (gb + j < CAND_CAP) g_cand[gb + j] = buf[j];
        }
    }
    __syncthreads();
    for (int i = threadIdx.x; i < 8192; i += blockDim.x) {
        unsigned c = sh[i];
        if (c) atomicAdd(&g_hist[i], c);
    }
}

// pass 2: histogram bits[5:0] over compacted candidates; full-scan fallback on overflow
__global__ void k_hist2c() {
    __shared__ unsigned sh[64];
    if (threadIdx.x < 64) sh[threadIdx.x] = 0u;
    __syncthreads();
    const unsigned key = g_key;
    const unsigned kp2 = key >> 6;
    const unsigned n = g_cnt;
    if (n <= CAND_CAP) {
        for (unsigned i = blockIdx.x * blockDim.x + threadIdx.x; i < n;
             i += gridDim.x * blockDim.x) {
            unsigned b = g_cand[i];
            if ((b >> 6) == kp2) atomicAdd(&sh[b & 63u], 1u);
        }
    } else {
        const int t = threadIdx.x;
        for (int tl = blockIdx.x; tl < NUT; tl += (int)gridDim.x) {
            int bi, bj; tile_decode(tl, bi, bj);
            const unsigned wgt = (bi == bj) ? 1u : 2u;
            const size_t base = (size_t)bi * 128 * NN + bj * 128;
            #pragma unroll 4
            for (int i = 0; i < 16; i++) {
                int lin = i * 256 + t;
                int r = lin >> 5, c = lin & 31;
                float4 v = __ldg((const float4*)(g_sim + base + (size_t)r * NN) + c);
                float vv[4] = {v.x, v.y, v.z, v.w};
                #pragma unroll
                for (int u = 0; u < 4; u++) {
                    unsigned b = __float_as_uint(vv[u]);
                    if ((b >> 6) == kp2) atomicAdd(&sh[b & 63u], wgt);
                }
            }
        }
    }
    __syncthreads();
    if (threadIdx.x < 64) {
        unsigned c = sh[threadIdx.x];
        if (c) atomicAdd(&g_hist[threadIdx.x], c);
    }
}

// parallel-prefix scan: 1024 threads, shfl warp-scan + 32-word combine
__global__ void __launch_bounds__(1024) k_scan(int nbins, int shift) {
    __shared__ unsigned s[8192];
    __shared__ unsigned wsum[32];
    int t = threadIdx.x;                    // 1024 threads, single block
    for (int i = t; i < nbins; i += 1024) s[i] = g_hist[i];
    __syncthreads();
    int per = (nbins + 1023) / 1024;
    int lo = t * per; if (lo > nbins) lo = nbins;
    int hi = lo + per; if (hi > nbins) hi = nbins;
    unsigned mysum = 0;
    for (int i = lo; i < hi; i++) mysum += s[i];
    unsigned inc = mysum;
    #pragma unroll
    for (int o = 1; o < 32; o <<= 1) {
        unsigned v = __shfl_up_sync(0xffffffffu, inc, o);
        if ((t & 31) >= o) inc += v;
    }
    if ((t & 31) == 31) wsum[t >> 5] = inc;
    __syncthreads();
    unsigned wpre = 0;
    #pragma unroll
    for (int i = 0; i < 32; i++) if (i < (t >> 5)) wpre += wsum[i];
    unsigned pre = wpre + inc - mysum;      // exclusive prefix for this thread
    unsigned rem = g_rem;
    __syncthreads();                        // all read g_rem before the winner writes it
    if (mysum > 0 && rem >= pre && rem < pre + mysum) {
        unsigned r = rem - pre;
        for (int i = lo; i < hi; i++) {
            if (r < s[i]) { g_key |= ((unsigned)i) << shift; g_rem = r; break; }
            r -= s[i];
        }
    }
    __syncthreads();
    for (int i = t; i < nbins; i += 1024) g_hist[i] = 0u;  // ready for next pass / replay
}

// ----------------- 4. adjacency from upper tiles: direct + bit-transposed mirror --------
__global__ void __launch_bounds__(256) k_adj_tile() {
    __shared__ unsigned bits[128][4];
    int bi, bj; tile_decode(blockIdx.x, bi, bj);
    const int t = threadIdx.x, lane = t & 31, w = t >> 5;   // 8 warps
    const float eps = __uint_as_float(g_key);
    const int r0 = bi * 128, c0 = bj * 128;
    const int cw0 = c0 >> 5, rw0 = r0 >> 5;

    #pragma unroll
    for (int rr = 0; rr < 16; rr++) {
        int r = w * 16 + rr;
        const float* srow = g_sim + (size_t)(r0 + r) * NN + c0;
        #pragma unroll
        for (int q = 0; q < 4; q++) {
            float v = srow[q * 32 + lane];
            unsigned m = __ballot_sync(0xffffffffu, v >= eps);
            if (lane == 0) {
                g_adj[(r0 + r) * NWORD + cw0 + q] = m;
                bits[r][q] = m;
            }
        }
    }
    if (bi == bj) return;
    __syncthreads();

    const int qr = w >> 1;                  // warps 0..7 -> qr 0..3
    const int chalf = (w & 1) * 64;         // c range [chalf, chalf+64)
    unsigned wa = bits[qr * 32 + lane][(chalf >> 5) + 0];
    unsigned wb = bits[qr * 32 + lane][(chalf >> 5) + 1];
    #pragma unroll
    for (int cc = 0; cc < 32; cc++) {
        unsigned m = __ballot_sync(0xffffffffu, (wa >> cc) & 1u);
        if (lane == 0) g_adj[(c0 + chalf + cc) * NWORD + rw0 + qr] = m;
    }
    #pragma unroll
    for (int cc = 0; cc < 32; cc++) {
        unsigned m = __ballot_sync(0xffffffffu, (wb >> cc) & 1u);
        if (lane == 0) g_adj[(c0 + chalf + 32 + cc) * NWORD + rw0 + qr] = m;
    }
}

// ----------------- 4b. degrees: popc over adjacency rows -----------------
__global__ void k_deg() {
    int row  = (blockIdx.x * blockDim.x + threadIdx.x) >> 5;  // one warp / row
    int lane = threadIdx.x & 31;
    if (row >= NN) return;
    const unsigned* ar = g_adj + row * NWORD;
    int cnt = 0;
    #pragma unroll
    for (int i = 0; i < 8; i++) cnt += __popc(ar[lane + i * 32]);
    #pragma unroll
    for (int o = 16; o; o >>= 1) cnt += __shfl_xor_sync(0xffffffffu, cnt, o);
    if (lane == 0) g_inv[row] = 1.0f / fmaxf((float)cnt, 1.0f);
}

// ----------------- 5. fused dense / SAGE GEMM, FFMA2 inner ------------------------------
__global__ void __launch_bounds__(256) k_sage(
    const float* __restrict__ A1, const float* __restrict__ W1, int K1,
    const float* __restrict__ A2, const float* __restrict__ W2, int K2,
    const float* __restrict__ bias, const float* __restrict__ res,
    float* __restrict__ out, __half* __restrict__ out16, int relu)
{
    __shared__ float As[16][132];
    __shared__ float Bs[16][68];
    const int t  = threadIdx.x;
    const int tx = t & 15, ty = t >> 4;
    const int r0 = blockIdx.x * 128, c0 = blockIdx.y * 64;

    u64 acc2[8][2];
    #pragma unroll
    for (int i = 0; i < 8; i++) { acc2[i][0] = 0ull; acc2[i][1] = 0ull; }

    const float* Ap = A1; const float* Wp = W1; int K = K1;
    for (int phase = 0; phase < 2; phase++) {
        if (phase == 1) {
            if (A2 == nullptr) break;
            Ap = A2; Wp = W2; K = K2;
        }
        for (int k0 = 0; k0 < K; k0 += 16) {
            #pragma unroll
            for (int i = 0; i < 2; i++) {
                int lid = t + i * 256;
                int row = lid >> 2;             // 0..127
                int q   = lid & 3;
                float4 a = *(const float4*)(Ap + (size_t)(r0 + row) * K + k0 + q * 4);
                As[q*4+0][row] = a.x; As[q*4+1][row] = a.y;
                As[q*4+2][row] = a.z; As[q*4+3][row] = a.w;
            }
            {
                int kk = t >> 4, n4 = (t & 15) * 4;
                float4 b = *(const float4*)(Wp + (size_t)(k0 + kk) * HDIM + c0 + n4);
                Bs[kk][n4+0] = b.x; Bs[kk][n4+1] = b.y;
                Bs[kk][n4+2] = b.z; Bs[kk][n4+3] = b.w;
            }
            __syncthreads();
            #pragma unroll
            for (int kk = 0; kk < 16; kk++) {
                float a[8];
                *(float4*)&a[0] = *(const float4*)&As[kk][ty * 4];
                *(float4*)&a[4] = *(const float4*)&As[kk][64 + ty * 4];
                u64 bv[2];
                {
                    const u64* bp = (const u64*)&Bs[kk][tx * 4];
                    bv[0] = bp[0]; bv[1] = bp[1];
                }
                #pragma unroll
                for (int i = 0; i < 8; i++) {
                    u64 a2; DUP2(a2, a[i]);
                    FMA2(acc2[i][0], a2, bv[0]);
                    FMA2(acc2[i][1], a2, bv[1]);
                }
            }
            __syncthreads();
        }
    }
    float bvv[4];
    *(float4*)bvv = *(const float4*)(bias + c0 + tx * 4);
    #pragma unroll
    for (int i = 0; i < 8; i++) {
        int row = r0 + ((i >> 2) << 6) + ty * 4 + (i & 3);
        float v[4];
        UNPK(v[0], v[1], acc2[i][0]);
        UNPK(v[2], v[3], acc2[i][1]);
        #pragma unroll
        for (int j = 0; j < 4; j++) v[j] += bvv[j];
        if (res) {
            float4 rr = *(const float4*)(res + (size_t)row * HDIM + c0 + tx * 4);
            v[0] += rr.x; v[1] += rr.y; v[2] += rr.z; v[3] += rr.w;
        }
        if (relu) {
            #pragma unroll
            for (int j = 0; j < 4; j++) v[j] = fmaxf(v[j], 0.f);
        }
        *(float4*)(out + (size_t)row * HDIM + c0 + tx * 4) = make_float4(v[0], v[1], v[2], v[3]);
        if (out16) {
            __half2 h01 = __floats2half2_rn(v[0], v[1]);
            __half2 h23 = __floats2half2_rn(v[2], v[3]);
            uint2 pk;
            pk.x = *(unsigned*)&h01;
            pk.y = *(unsigned*)&h23;
            *(uint2*)(out16 + (size_t)row * HDIM + c0 + tx * 4) = pk;
        }
    }
}

// ----------------- 6. aggregation as dense A@H via tensor cores (wmma) ------------------
// Block: 64 dst rows x 256 cols. A tiles expanded from the adjacency BITMASK into an
// smem fp16 tile (no dense-A materialization). H streamed in 64-row chunks through smem.
// 8 warps: warp w -> m-tile (w&3), n-half (w>>2). Output written UNSCALED; k_scale
// applies 1/deg afterwards.
__global__ void __launch_bounds__(256) k_aggw(const __half* __restrict__ h,
                                              float* __restrict__ out) {
    __shared__ __half Hs[AGG_KC][HDIM + 8];    // 64 x 264 fp16 = 33.8 KB
    __shared__ __half Am[AGG_BM][AGG_KC + 8];  // 64 x 72  fp16 =  9.2 KB
    const int t  = threadIdx.x;
    const int w  = t >> 5;
    const int m0 = blockIdx.x * AGG_BM;
    const int mt = w & 3;                      // m-tile (16 rows)
    const int nh = w >> 2;                     // n-half (128 cols)

    wmma::fragment<wmma::accumulator, 16, 16, 16, float> acc[8];
    #pragma unroll
    for (int j = 0; j < 8; j++) wmma::fill_fragment(acc[j], 0.0f);

    for (int kc = 0; kc < NN; kc += AGG_KC) {
        // stage H chunk: 64 rows x 256 halves (coalesced uint4)
        #pragma unroll
        for (int i = 0; i < 8; i++) {
            int lin = t + i * 256;             // 0..2047
            int r = lin >> 5, c = lin & 31;
            uint4 v = __ldg((const uint4*)(h + (size_t)(kc + r) * HDIM) + c);
            *(uint4*)(&Hs[r][c * 8]) = v;
        }
        // expand A tile from bitmask: thread t -> row t>>2, 16-bit group q = t&3
        {
            int r = t >> 2, q = t & 3;
            unsigned word = g_adj[(m0 + r) * NWORD + (kc >> 5) + (q >> 1)];
            unsigned bits = (word >> ((q & 1) * 16)) & 0xFFFFu;
            unsigned pk[8];
            #pragma unroll
            for (int b = 0; b < 8; b++) {
                unsigned lo = (bits >> (2 * b)) & 1u;
                unsigned hi = (bits >> (2 * b + 1)) & 1u;
                pk[b] = lo * 0x3C00u | hi * 0x3C000000u;   // {1.0h/0, 1.0h/0}
            }
            *(uint4*)(&Am[r][q * 16])     = *(uint4*)&pk[0];
            *(uint4*)(&Am[r][q * 16 + 8]) = *(uint4*)&pk[4];
        }
        __syncthreads();
        #pragma unroll
        for (int ks = 0; ks < AGG_KC; ks += 16) {
            wmma::fragment<wmma::matrix_a, 16, 16, 16, __half, wmma::row_major> af;
            wmma::load_matrix_sync(af, &Am[mt * 16][ks], AGG_KC + 8);
            #pragma unroll
            for (int j = 0; j < 8; j++) {
                wmma::fragment<wmma::matrix_b, 16, 16, 16, __half, wmma::row_major> bf;
                wmma::load_matrix_sync(bf, &Hs[ks][nh * 128 + j * 16], HDIM + 8);
                wmma::mma_sync(acc[j], af, bf, acc[j]);
            }
        }
        __syncthreads();
    }
    // store unscaled sums
    #pragma unroll
    for (int j = 0; j < 8; j++) {
        float* dst = out + (size_t)(m0 + mt * 16) * HDIM + nh * 128 + j * 16;
        wmma::store_matrix_sync(dst, acc[j], HDIM, wmma::mem_row_major);
    }
}

// in-place row scaling by 1/deg: a[row][*] *= g_inv[row]
__global__ void k_scale(float* __restrict__ a) {
    int i = blockIdx.x * blockDim.x + threadIdx.x;   // over NN*HDIM/4 float4s
    float inv = g_inv[i >> 6];                       // 64 float4 per row
    float4 v = ((float4*)a)[i];
    v.x *= inv; v.y *= inv; v.z *= inv; v.w *= inv;
    ((float4*)a)[i] = v;
}

// ----------------- 7. width-1 aggregation with fused epilogues -----------------
// mode 0: out[row] = relu(agg1(y)[row] + w0 + g_yr[row])
// mode 1: out[row] = sigmoid(agg1(y)[row]*w0 + w1 + y[row]*w2 + g_sc[row])
template <int MODE>
__global__ void __launch_bounds__(256) k_agg1f(const float* __restrict__ y,
                                               const float* __restrict__ w0,
                                               const float* __restrict__ w1,
                                               const float* __restrict__ w2,
                                               float* __restrict__ out) {
    __shared__ float sred[8];
    int row = blockIdx.x, t = threadIdx.x;
    unsigned m = g_adj[row * NWORD + t];
    int base = t << 5;
    float acc = 0.f;
    while (m) {
        int b = __ffs(m) - 1;
        m &= m - 1;
        acc += __ldg(&y[base + b]);
    }
    #pragma unroll
    for (int o = 16; o; o >>= 1) acc += __shfl_xor_sync(0xffffffffu, acc, o);
    if ((t & 31) == 0) sred[t >> 5] = acc;
    __syncthreads();
    if (t == 0) {
        float v = 0.f;
        #pragma unroll
        for (int i = 0; i < 8; i++) v += sred[i];
        float a = v * g_inv[row];
        if (MODE == 0) {
            out[row] = fmaxf(a + w0[0] + g_yr[row], 0.f);
        } else {
            float o = a * w0[0] + w1[0] + y[row] * w2[0] + g_sc[row];
            out[row] = 1.0f / (1.0f + expf(-o));
        }
    }
}

// ----------------- 8. three fused matvecs -----------------
__global__ void k_matvec3(const float* __restrict__ h,
                          const float* __restrict__ wl, const float* __restrict__ wr,
                          const float* __restrict__ wsc, const float* __restrict__ oscb) {
    int gw   = (blockIdx.x * blockDim.x + threadIdx.x) >> 5;   // one warp per row
    int lane = threadIdx.x & 31;
    if (gw >= NN) return;
    const float* hr = h + (size_t)gw * HDIM;
    float sl = 0.f, sr = 0.f, ss = 0.f;
    #pragma unroll
    for (int u = 0; u < HDIM / 32; u++) {
        int idx = lane + u * 32;
        float v = hr[idx];
        sl += v * __ldg(&wl[idx]);
        sr += v * __ldg(&wr[idx]);
        ss += v * __ldg(&wsc[idx]);
    }
    #pragma unroll
    for (int o = 16; o; o >>= 1) {
        sl += __shfl_xor_sync(0xffffffffu, sl, o);
        sr += __shfl_xor_sync(0xffffffffu, sr, o);
        ss += __shfl_xor_sync(0xffffffffu, ss, o);
    }
    if (lane == 0) {
        g_yl[gw] = sl;
        g_yr[gw] = sr;
        g_sc[gw] = ss + oscb[0];
    }
}

// ========================= launch =========================
extern "C" void kernel_launch(void* const* d_in, const int* in_sizes, int n_in,
                              void* d_out, int out_size) {
    const float* x     = (const float*)d_in[0];
    const float* w_in  = (const float*)d_in[1];
    const float* b_in  = (const float*)d_in[2];
    const float* h1_wl = (const float*)d_in[3];
    const float* h1_bl = (const float*)d_in[4];
    const float* h1_wr = (const float*)d_in[5];
    const float* h2_wl = (const float*)d_in[6];
    const float* h2_bl = (const float*)d_in[7];
    const float* h2_wr = (const float*)d_in[8];
    const float* o1_wl = (const float*)d_in[9];
    const float* o1_bl = (const float*)d_in[10];
    const float* o1_wr = (const float*)d_in[11];
    const float* o2_wl = (const float*)d_in[12];
    const float* o2_bl = (const float*)d_in[13];
    const float* o2_wr = (const float*)d_in[14];
    const float* osc_w = (const float*)d_in[15];
    const float* osc_b = (const float*)d_in[16];
    float* out = (float*)d_out;

    // resolve scratch addresses
    float  *p_h0, *p_h1, *p_h2, *p_agg, *p_yl, *p_o1;
    __half *p_h0f, *p_h1f;
    cudaGetSymbolAddress((void**)&p_h0,  g_h0);
    cudaGetSymbolAddress((void**)&p_h1,  g_h1);
    cudaGetSymbolAddress((void**)&p_h2,  g_h2);
    cudaGetSymbolAddress((void**)&p_h0f, g_h0f);
    cudaGetSymbolAddress((void**)&p_h1f, g_h1f);
    cudaGetSymbolAddress((void**)&p_agg, g_agg);
    cudaGetSymbolAddress((void**)&p_yl,  g_yl);
    cudaGetSymbolAddress((void**)&p_o1,  g_o1v);

    // 1) normalize
    k_normalize<<<NN, DIN>>>(x);
    // 2) similarity matrix, upper-triangle tiles only
    dim3 gs(NTILE, NTILE);
    k_simgemm_sym<<<gs, 256>>>();
    // 3) exact quantile: 3-pass radix select; pass 1 compacts candidates (block-staged)
    k_init_sel<<<1, 256>>>();
    k_hist<0><<<1040, 256>>>();
    k_scan<<<1, 1024>>>(8192, 19);
    k_hist<1><<<1040, 256>>>();
    k_scan<<<1, 1024>>>(8192, 6);
    k_hist2c<<<1040, 256>>>();
    k_scan<<<1, 1024>>>(64, 0);
    // 4) adjacency from upper tiles (direct + bit-transposed mirror), then degrees
    k_adj_tile<<<NUT, 256>>>();
    k_deg<<<NN * 32 / 256, 256>>>();
    // 5) h0 = relu(x @ w_in + b_in)   (+ fp16 copy for aggregation)
    dim3 gd(NN / 128, HDIM / 64);
    k_sage<<<gd, 256>>>(x, w_in, DIN, nullptr, nullptr, 0, b_in, nullptr, p_h0, p_h0f, 1);
    // 6) h1 = relu(agg(h0) @ h1_wl + h1_bl + h0 @ h1_wr)   — agg via tensor cores
    k_aggw<<<NN / AGG_BM, 256>>>(p_h0f, p_agg);
    k_scale<<<NN * HDIM / 4 / 256, 256>>>(p_agg);
    k_sage<<<gd, 256>>>(p_agg, h1_wl, HDIM, p_h0, h1_wr, HDIM, h1_bl, nullptr, p_h1, p_h1f, 1);
    // 7) h2 = relu(agg(h1) @ h2_wl + h2_bl + h1 @ h2_wr + h0)
    k_aggw<<<NN / AGG_BM, 256>>>(p_h1f, p_agg);
    k_scale<<<NN * HDIM / 4 / 256, 256>>>(p_agg);
    k_sage<<<gd, 256>>>(p_agg, h2_wl, HDIM, p_h1, h2_wr, HDIM, h2_bl, p_h0, p_h2, nullptr, 1);
    // 8) output heads: agg(h2)@wl == agg(h2@wl)  (linearity) -> scalar aggregations
    k_matvec3<<<NN * 32 / 256, 256>>>(p_h2, o1_wl, o1_wr, osc_w, osc_b);
    // o1 = relu(agg1(yl) + o1_bl + yr)          (fused epilogue)
    k_agg1f<0><<<NN, 256>>>(p_yl, o1_bl, nullptr, nullptr, p_o1);
    // out = sigmoid(agg1(o1)*o2_wl + o2_bl + o1*o2_wr + sc)   (fused epilogue)
    k_agg1f<1><<<NN, 256>>>(p_o1, o2_wl, o2_bl, o2_wr, out);
}

// round 15
// speedup vs baseline: 1.1423x; 1.1423x over previous
#include <cuda_runtime.h>
#include <cuda_fp16.h>
#include <mma.h>
#include <math.h>

using namespace nvcuda;

#define NN    8192
#define DIN   128
#define HDIM  256
#define NWORD 256               // 8192/32 mask words per row
#define NTILE 64                // 8192/128 tile grid
#define NUT   2080              // upper-triangle tile count (64*65/2)
#define KRANK 63753420u         // nearest-rank index of 0.95 quantile over N*N values
#define CAND_CAP (1u << 24)     // 16M candidate slots (64 MB)

typedef unsigned long long u64;

// packed f32x2 helpers (sm_103a): 2 independent fp32 FMAs per instruction, bit-identical
#define FMA2(d, a, b)   asm("fma.rn.f32x2 %0, %1, %2, %0;" : "+l"(d) : "l"(a), "l"(b))
#define DUP2(d, s)      asm("mov.b64 %0, {%1, %1};" : "=l"(d) : "f"(s))
#define UNPK(lo, hi, s) asm("mov.b64 {%0, %1}, %2;" : "=f"(lo), "=f"(hi) : "l"(s))

// ----------------- device scratch (static globals; no runtime allocation) -----------------
__device__ __half   g_xh  [NN * DIN];          // fp16 hi part of normalized x (2 MB)
__device__ __half   g_xl  [NN * DIN];          // fp16 lo part (residual)      (2 MB)
__device__ float    g_sim [(size_t)NN * NN];   // |xn@xn^T|, UPPER TILES ONLY valid
__device__ unsigned g_adj [NN * NWORD];        // adjacency bitmask       (8 MB)
__device__ float    g_inv [NN];                // 1/deg
__device__ float    g_h0  [NN * HDIM];
__device__ float    g_h1  [NN * HDIM];
__device__ float    g_h2  [NN * HDIM];
__device__ __half   g_h0f [NN * HDIM];         // fp16 copy for aggregation
__device__ __half   g_h1f [NN * HDIM];
__device__ float    g_agg [NN * HDIM];
__device__ float    g_yl  [NN];
__device__ float    g_yr  [NN];
__device__ float    g_sc  [NN];
__device__ float    g_o1v [NN];
__device__ unsigned g_hist[8192];
__device__ unsigned g_cand[CAND_CAP];          // compacted pass-1 candidates
__device__ unsigned g_cnt;
__device__ unsigned g_key;
__device__ unsigned g_rem;

// decode linear upper-triangle tile index -> (bi, bj), bi <= bj
__device__ __forceinline__ void tile_decode(int tl, int& bi, int& bj) {
    int b = 0, rem = tl;
    while (rem >= NTILE - b) { rem -= NTILE - b; b++; }
    bi = b; bj = b + rem;
}

// ----------------- 1. row-normalize x; emit split-fp16 (hi + lo == fp32 xn) -------------
__global__ void k_normalize(const float* __restrict__ x) {
    int row = blockIdx.x;
    int t   = threadIdx.x;                 // 128 threads = 1 col each
    float v = x[row * DIN + t];
    float s = v * v;
    #pragma unroll
    for (int o = 16; o; o >>= 1) s += __shfl_xor_sync(0xffffffffu, s, o);
    __shared__ float ws[4];
    if ((t & 31) == 0) ws[t >> 5] = s;
    __syncthreads();
    float nrm = fmaxf(sqrtf(ws[0] + ws[1] + ws[2] + ws[3]), 1e-8f);
    float xn = v / nrm;
    __half hi = __float2half_rn(xn);
    __half lo = __float2half_rn(xn - __half2float(hi));
    g_xh[row * DIN + t] = hi;
    g_xl[row * DIN + t] = lo;
}

// ----------------- 2. sim = |xn @ xn^T| via tensor cores, split-fp16 3-product ----------
// Upper-triangle 128x128 tiles. Phases: (hi,hi), (lo,hi), (hi,lo); fp32 accumulate.
// Error ~2^-22 (lo*lo dropped) — fp32-reassociation magnitude.
// 8 warps: warp w -> mt pair (w&3)*2,(w&3)*2+1 ; nt quad (w>>2)*4..+3.
__global__ void __launch_bounds__(256) k_simgemm_w() {
    const int bi = blockIdx.x, bj = blockIdx.y;
    if (bj < bi) return;

    extern __shared__ __half sh2[];
    __half* Ah = sh2;                      // [128][136]
    __half* Bh = sh2 + 128 * 136;          // [128][136]

    const int t = threadIdx.x, w = t >> 5;
    const int mtp = (w & 3) * 2;           // this warp's two m-tiles
    const int nq  = (w >> 2) * 4;          // this warp's four n-tiles
    const int r0 = bi * 128, c0 = bj * 128;

    wmma::fragment<wmma::accumulator, 16, 16, 16, float> acc[2][4];
    #pragma unroll
    for (int i = 0; i < 2; i++)
        #pragma unroll
        for (int j = 0; j < 4; j++) wmma::fill_fragment(acc[i][j], 0.0f);

    #pragma unroll
    for (int phase = 0; phase < 3; phase++) {
        const __half* asrc = (phase == 1) ? g_xl : g_xh;
        const __half* bsrc = (phase == 2) ? g_xl : g_xh;
        const bool sA = true;                       // A restaged every phase
        const bool sB = (phase != 1);               // B unchanged hi->lo phase 1
        __syncthreads();
        #pragma unroll
        for (int i = 0; i < 8; i++) {
            int lin = t + i * 256;                  // 0..2047
            int r = lin >> 4, c = lin & 15;         // 16 uint4 per 128-half row
            if (sA)
                *(uint4*)(Ah + r * 136 + c * 8) =
                    *(const uint4*)(asrc + (size_t)(r0 + r) * DIN + c * 8);
            if (sB)
                *(uint4*)(Bh + r * 136 + c * 8) =
                    *(const uint4*)(bsrc + (size_t)(c0 + r) * DIN + c * 8);
        }
        __syncthreads();
        #pragma unroll
        for (int k = 0; k < 8; k++) {
            wmma::fragment<wmma::matrix_a, 16, 16, 16, __half, wmma::row_major> af[2];
            wmma::load_matrix_sync(af[0], Ah + (mtp    ) * 16 * 136 + k * 16, 136);
            wmma::load_matrix_sync(af[1], Ah + (mtp + 1) * 16 * 136 + k * 16, 136);
            #pragma unroll
            for (int j = 0; j < 4; j++) {
                // B[k][n] = xn[c0+n][k]  ->  col_major at Bh + n*136 + k
                wmma::fragment<wmma::matrix_b, 16, 16, 16, __half, wmma::col_major> bf;
                wmma::load_matrix_sync(bf, Bh + (nq + j) * 16 * 136 + k * 16, 136);
                wmma::mma_sync(acc[0][j], af[0], bf, acc[0][j]);
                wmma::mma_sync(acc[1][j], af[1], bf, acc[1][j]);
            }
        }
    }
    #pragma unroll
    for (int i = 0; i < 2; i++)
        #pragma unroll
        for (int j = 0; j < 4; j++) {
            #pragma unroll
            for (int e = 0; e < acc[i][j].num_elements; e++)
                acc[i][j].x[e] = fabsf(acc[i][j].x[e]);
            wmma::store_matrix_sync(
                g_sim + (size_t)(r0 + (mtp + i) * 16) * NN + c0 + (nq + j) * 16,
                acc[i][j], NN, wmma::mem_row_major);
        }
}

// ----------------- 3. exact k-th order statistic: radix select over UPPER tiles ---------
__global__ void k_init_sel() {
    if (threadIdx.x == 0) { g_key = 0u; g_rem = KRANK; g_cnt = 0u; }
    for (int i = threadIdx.x; i < 8192; i += blockDim.x) g_hist[i] = 0u;
}

template <int PASS>
__global__ void k_hist() {
    __shared__ unsigned sh[8192];
    __shared__ unsigned buf[(PASS == 1) ? 4096 : 1];
    __shared__ unsigned bcnt, gbase;
    for (int i = threadIdx.x; i < 8192; i += blockDim.x) sh[i] = 0u;
    if (threadIdx.x == 0) bcnt = 0u;
    __syncthreads();
    const unsigned key = g_key;
    const unsigned kp1 = key >> 19;
    const int t = threadIdx.x;
    for (int tl = blockIdx.x; tl < NUT; tl += gridDim.x) {
        int bi, bj; tile_decode(tl, bi, bj);
        const unsigned wgt = (bi == bj) ? 1u : 2u;
        const size_t base = (size_t)bi * 128 * NN + bj * 128;
        #pragma unroll 4
        for (int i = 0; i < 16; i++) {
            int lin = i * 256 + t;
            int r = lin >> 5, c = lin & 31;
            float4 v = __ldg((const float4*)(g_sim + base + (size_t)r * NN) + c);
            float vv[4] = {v.x, v.y, v.z, v.w};
            #pragma unroll
            for (int u = 0; u < 4; u++) {
                unsigned b = __float_as_uint(vv[u]);
                if (PASS == 0) {
                    atomicAdd(&sh[b >> 19], wgt);
                } else {
                    if ((b >> 19) == kp1) {
                        atomicAdd(&sh[(b >> 6) & 8191u], wgt);
                        unsigned slot = atomicAdd(&bcnt, wgt);   // smem atomic, rare
                        buf[slot] = b;
                        if (wgt == 2u) buf[slot + 1] = b;
                    }
                }
            }
            if (PASS == 1) {
                __syncthreads();
                if (bcnt > 2048u) {              // flush: ONE global atomic per ~2K cands
                    if (t == 0) gbase = atomicAdd(&g_cnt, bcnt);
                    __syncthreads();
                    unsigned n = bcnt, gb = gbase;
                    for (unsigned j = t; j < n; j += 256)
                        if (gb + j < CAND_CAP) g_cand[gb + j] = buf[j];
                    __syncthreads();
                    if (t == 0) bcnt = 0u;
                    __syncthreads();
                }
            }
        }
    }
    if (PASS == 1) {                              // final flush
        __syncthreads();
        if (bcnt > 0u) {
            if (t == 0) gbase = atomicAdd(&g_cnt, bcnt);
            __syncthreads();
            unsigned n = bcnt, gb = gbase;
            for (unsigned j = t; j < n; j += 256)
                if (gb + j < CAND_CAP) g_cand[gb + j] = buf[j];
        }
    }
    __syncthreads();
    for (int i = threadIdx.x; i < 8192; i += blockDim.x) {
        unsigned c = sh[i];
        if (c) atomicAdd(&g_hist[i], c);
    }
}

// pass 2: histogram bits[5:0] over compacted candidates; full-scan fallback on overflow
__global__ void k_hist2c() {
    __shared__ unsigned sh[64];
    if (threadIdx.x < 64) sh[threadIdx.x] = 0u;
    __syncthreads();
    const unsigned key = g_key;
    const unsigned kp2 = key >> 6;
    const unsigned n = g_cnt;
    if (n <= CAND_CAP) {
        for (unsigned i = blockIdx.x * blockDim.x + threadIdx.x; i < n;
             i += gridDim.x * blockDim.x) {
            unsigned b = g_cand[i];
            if ((b >> 6) == kp2) atomicAdd(&sh[b & 63u], 1u);
        }
    } else {
        const int t = threadIdx.x;
        for (int tl = blockIdx.x; tl < NUT; tl += (int)gridDim.x) {
            int bi, bj; tile_decode(tl, bi, bj);
            const unsigned wgt = (bi == bj) ? 1u : 2u;
            const size_t base = (size_t)bi * 128 * NN + bj * 128;
            #pragma unroll 4
            for (int i = 0; i < 16; i++) {
                int lin = i * 256 + t;
                int r = lin >> 5, c = lin & 31;
                float4 v = __ldg((const float4*)(g_sim + base + (size_t)r * NN) + c);
                float vv[4] = {v.x, v.y, v.z, v.w};
                #pragma unroll
                for (int u = 0; u < 4; u++) {
                    unsigned b = __float_as_uint(vv[u]);
                    if ((b >> 6) == kp2) atomicAdd(&sh[b & 63u], wgt);
                }
            }
        }
    }
    __syncthreads();
    if (threadIdx.x < 64) {
        unsigned c = sh[threadIdx.x];
        if (c) atomicAdd(&g_hist[threadIdx.x], c);
    }
}

// parallel-prefix scan: 1024 threads, shfl warp-scan + 32-word combine
__global__ void __launch_bounds__(1024) k_scan(int nbins, int shift) {
    __shared__ unsigned s[8192];
    __shared__ unsigned wsum[32];
    int t = threadIdx.x;                    // 1024 threads, single block
    for (int i = t; i < nbins; i += 1024) s[i] = g_hist[i];
    __syncthreads();
    int per = (nbins + 1023) / 1024;
    int lo = t * per; if (lo > nbins) lo = nbins;
    int hi = lo + per; if (hi > nbins) hi = nbins;
    unsigned mysum = 0;
    for (int i = lo; i < hi; i++) mysum += s[i];
    unsigned inc = mysum;
    #pragma unroll
    for (int o = 1; o < 32; o <<= 1) {
        unsigned v = __shfl_up_sync(0xffffffffu, inc, o);
        if ((t & 31) >= o) inc += v;
    }
    if ((t & 31) == 31) wsum[t >> 5] = inc;
    __syncthreads();
    unsigned wpre = 0;
    #pragma unroll
    for (int i = 0; i < 32; i++) if (i < (t >> 5)) wpre += wsum[i];
    unsigned pre = wpre + inc - mysum;      // exclusive prefix for this thread
    unsigned rem = g_rem;
    __syncthreads();                        // all read g_rem before the winner writes it
    if (mysum > 0 && rem >= pre && rem < pre + mysum) {
        unsigned r = rem - pre;
        for (int i = lo; i < hi; i++) {
            if (r < s[i]) { g_key |= ((unsigned)i) << shift; g_rem = r; break; }
            r -= s[i];
        }
    }
    __syncthreads();
    for (int i = t; i < nbins; i += 1024) g_hist[i] = 0u;  // ready for next pass / replay
}

// ----------------- 4. adjacency from upper tiles: direct + bit-transposed mirror --------
__global__ void __launch_bounds__(256) k_adj_tile() {
    __shared__ unsigned bits[128][4];
    int bi, bj; tile_decode(blockIdx.x, bi, bj);
    const int t = threadIdx.x, lane = t & 31, w = t >> 5;   // 8 warps
    const float eps = __uint_as_float(g_key);
    const int r0 = bi * 128, c0 = bj * 128;
    const int cw0 = c0 >> 5, rw0 = r0 >> 5;

    #pragma unroll
    for (int rr = 0; rr < 16; rr++) {
        int r = w * 16 + rr;
        const float* srow = g_sim + (size_t)(r0 + r) * NN + c0;
        #pragma unroll
        for (int q = 0; q < 4; q++) {
            float v = srow[q * 32 + lane];
            unsigned m = __ballot_sync(0xffffffffu, v >= eps);
            if (lane == 0) {
                g_adj[(r0 + r) * NWORD + cw0 + q] = m;
                bits[r][q] = m;
            }
        }
    }
    if (bi == bj) return;
    __syncthreads();

    const int qr = w >> 1;                  // warps 0..7 -> qr 0..3
    const int chalf = (w & 1) * 64;         // c range [chalf, chalf+64)
    unsigned wa = bits[qr * 32 + lane][(chalf >> 5) + 0];
    unsigned wb = bits[qr * 32 + lane][(chalf >> 5) + 1];
    #pragma unroll
    for (int cc = 0; cc < 32; cc++) {
        unsigned m = __ballot_sync(0xffffffffu, (wa >> cc) & 1u);
        if (lane == 0) g_adj[(c0 + chalf + cc) * NWORD + rw0 + qr] = m;
    }
    #pragma unroll
    for (int cc = 0; cc < 32; cc++) {
        unsigned m = __ballot_sync(0xffffffffu, (wb >> cc) & 1u);
        if (lane == 0) g_adj[(c0 + chalf + 32 + cc) * NWORD + rw0 + qr] = m;
    }
}

// ----------------- 4b. degrees: popc over adjacency rows -----------------
__global__ void k_deg() {
    int row  = (blockIdx.x * blockDim.x + threadIdx.x) >> 5;  // one warp / row
    int lane = threadIdx.x & 31;
    if (row >= NN) return;
    const unsigned* ar = g_adj + row * NWORD;
    int cnt = 0;
    #pragma unroll
    for (int i = 0; i < 8; i++) cnt += __popc(ar[lane + i * 32]);
    #pragma unroll
    for (int o = 16; o; o >>= 1) cnt += __shfl_xor_sync(0xffffffffu, cnt, o);
    if (lane == 0) g_inv[row] = 1.0f / fmaxf((float)cnt, 1.0f);
}

// ----------------- 5. fused dense / SAGE GEMM, FFMA2 inner ------------------------------
__global__ void __launch_bounds__(256) k_sage(
    const float* __restrict__ A1, const float* __restrict__ W1, int K1,
    const float* __restrict__ A2, const float* __restrict__ W2, int K2,
    const float* __restrict__ bias, const float* __restrict__ res,
    float* __restrict__ out, __half* __restrict__ out16, int relu)
{
    __shared__ float As[16][132];
    __shared__ float Bs[16][68];
    const int t  = threadIdx.x;
    const int tx = t & 15, ty = t >> 4;
    const int r0 = blockIdx.x * 128, c0 = blockIdx.y * 64;

    u64 acc2[8][2];
    #pragma unroll
    for (int i = 0; i < 8; i++) { acc2[i][0] = 0ull; acc2[i][1] = 0ull; }

    const float* Ap = A1; const float* Wp = W1; int K = K1;
    for (int phase = 0; phase < 2; phase++) {
        if (phase == 1) {
            if (A2 == nullptr) break;
            Ap = A2; Wp = W2; K = K2;
        }
        for (int k0 = 0; k0 < K; k0 += 16) {
            #pragma unroll
            for (int i = 0; i < 2; i++) {
                int lid = t + i * 256;
                int row = lid >> 2;             // 0..127
                int q   = lid & 3;
                float4 a = *(const float4*)(Ap + (size_t)(r0 + row) * K + k0 + q * 4);
                As[q*4+0][row] = a.x; As[q*4+1][row] = a.y;
                As[q*4+2][row] = a.z; As[q*4+3][row] = a.w;
            }
            {
                int kk = t >> 4, n4 = (t & 15) * 4;
                float4 b = *(const float4*)(Wp + (size_t)(k0 + kk) * HDIM + c0 + n4);
                Bs[kk][n4+0] = b.x; Bs[kk][n4+1] = b.y;
                Bs[kk][n4+2] = b.z; Bs[kk][n4+3] = b.w;
            }
            __syncthreads();
            #pragma unroll
            for (int kk = 0; kk < 16; kk++) {
                float a[8];
                *(float4*)&a[0] = *(const float4*)&As[kk][ty * 4];
                *(float4*)&a[4] = *(const float4*)&As[kk][64 + ty * 4];
                u64 bv[2];
                {
                    const u64* bp = (const u64*)&Bs[kk][tx * 4];
                    bv[0] = bp[0]; bv[1] = bp[1];
                }
                #pragma unroll
                for (int i = 0; i < 8; i++) {
                    u64 a2; DUP2(a2, a[i]);
                    FMA2(acc2[i][0], a2, bv[0]);
                    FMA2(acc2[i][1], a2, bv[1]);
                }
            }
            __syncthreads();
        }
    }
    float bvv[4];
    *(float4*)bvv = *(const float4*)(bias + c0 + tx * 4);
    #pragma unroll
    for (int i = 0; i < 8; i++) {
        int row = r0 + ((i >> 2) << 6) + ty * 4 + (i & 3);
        float v[4];
        UNPK(v[0], v[1], acc2[i][0]);
        UNPK(v[2], v[3], acc2[i][1]);
        #pragma unroll
        for (int j = 0; j < 4; j++) v[j] += bvv[j];
        if (res) {
            float4 rr = *(const float4*)(res + (size_t)row * HDIM + c0 + tx * 4);
            v[0] += rr.x; v[1] += rr.y; v[2] += rr.z; v[3] += rr.w;
        }
        if (relu) {
            #pragma unroll
            for (int j = 0; j < 4; j++) v[j] = fmaxf(v[j], 0.f);
        }
        *(float4*)(out + (size_t)row * HDIM + c0 + tx * 4) = make_float4(v[0], v[1], v[2], v[3]);
        if (out16) {
            __half2 h01 = __floats2half2_rn(v[0], v[1]);
            __half2 h23 = __floats2half2_rn(v[2], v[3]);
            uint2 pk;
            pk.x = *(unsigned*)&h01;
            pk.y = *(unsigned*)&h23;
            *(uint2*)(out16 + (size_t)row * HDIM + c0 + tx * 4) = pk;
        }
    }
}

// ----------------- 6. mean aggregation, width 256, fp16 input, fp32 accumulate ----------
// (proven gather version: per-row, 4 groups x 64 threads, uint2 loads)
__global__ void __launch_bounds__(256) k_agg(const __half* __restrict__ h, float* __restrict__ out) {
    __shared__ unsigned sm[NWORD];
    __shared__ float red[4][HDIM];
    int row = blockIdx.x;
    int t   = threadIdx.x;
    int g   = t >> 6;                       // group 0..3 (its own 64 mask words)
    int c4  = t & 63;                       // this thread's 4-column slot
    sm[t] = g_adj[row * NWORD + t];
    __syncthreads();
    float4 acc = make_float4(0.f, 0.f, 0.f, 0.f);
    for (int w = g * 64; w < g * 64 + 64; w++) {
        unsigned m = sm[w];
        int base = w << 5;
        while (m) {
            int b0 = __ffs(m) - 1; m &= m - 1;
            uint2 r0 = __ldg((const uint2*)(h + ((size_t)(base + b0) << 8)) + c4);
            if (m) {
                int b1 = __ffs(m) - 1; m &= m - 1;
                uint2 r1 = __ldg((const uint2*)(h + ((size_t)(base + b1) << 8)) + c4);
                float2 a0 = __half22float2(*(__half2*)&r0.x);
                float2 a1 = __half22float2(*(__half2*)&r0.y);
                float2 b0v = __half22float2(*(__half2*)&r1.x);
                float2 b1v = __half22float2(*(__half2*)&r1.y);
                acc.x += a0.x + b0v.x; acc.y += a0.y + b0v.y;
                acc.z += a1.x + b1v.x; acc.w += a1.y + b1v.y;
            } else {
                float2 a0 = __half22float2(*(__half2*)&r0.x);
                float2 a1 = __half22float2(*(__half2*)&r0.y);
                acc.x += a0.x; acc.y += a0.y;
                acc.z += a1.x; acc.w += a1.y;
            }
        }
    }
    ((float4*)red[g])[c4] = acc;
    __syncthreads();
    if (t < 64) {
        float4 a0 = ((float4*)red[0])[t];
        float4 a1 = ((float4*)red[1])[t];
        float4 a2 = ((float4*)red[2])[t];
        float4 a3 = ((float4*)red[3])[t];
        float inv = g_inv[row];
        float4 r;
        r.x = (a0.x + a1.x + a2.x + a3.x) * inv;
        r.y = (a0.y + a1.y + a2.y + a3.y) * inv;
        r.z = (a0.z + a1.z + a2.z + a3.z) * inv;
        r.w = (a0.w + a1.w + a2.w + a3.w) * inv;
        ((float4*)(out + ((size_t)row << 8)))[t] = r;
    }
}

// ----------------- 7. width-1 aggregation with fused epilogues -----------------
// mode 0: out[row] = relu(agg1(y)[row] + w0 + g_yr[row])
// mode 1: out[row] = sigmoid(agg1(y)[row]*w0 + w1 + y[row]*w2 + g_sc[row])
template <int MODE>
__global__ void __launch_bounds__(256) k_agg1f(const float* __restrict__ y,
                                               const float* __restrict__ w0,
                                               const float* __restrict__ w1,
                                               const float* __restrict__ w2,
                                               float* __restrict__ out) {
    __shared__ float sred[8];
    int row = blockIdx.x, t = threadIdx.x;
    unsigned m = g_adj[row * NWORD + t];
    int base = t << 5;
    float acc = 0.f;
    while (m) {
        int b = __ffs(m) - 1;
        m &= m - 1;
        acc += __ldg(&y[base + b]);
    }
    #pragma unroll
    for (int o = 16; o; o >>= 1) acc += __shfl_xor_sync(0xffffffffu, acc, o);
    if ((t & 31) == 0) sred[t >> 5] = acc;
    __syncthreads();
    if (t == 0) {
        float v = 0.f;
        #pragma unroll
        for (int i = 0; i < 8; i++) v += sred[i];
        float a = v * g_inv[row];
        if (MODE == 0) {
            out[row] = fmaxf(a + w0[0] + g_yr[row], 0.f);
        } else {
            float o = a * w0[0] + w1[0] + y[row] * w2[0] + g_sc[row];
            out[row] = 1.0f / (1.0f + expf(-o));
        }
    }
}

// ----------------- 8. three fused matvecs -----------------
__global__ void k_matvec3(const float* __restrict__ h,
                          const float* __restrict__ wl, const float* __restrict__ wr,
                          const float* __restrict__ wsc, const float* __restrict__ oscb) {
    int gw   = (blockIdx.x * blockDim.x + threadIdx.x) >> 5;   // one warp per row
    int lane = threadIdx.x & 31;
    if (gw >= NN) return;
    const float* hr = h + (size_t)gw * HDIM;
    float sl = 0.f, sr = 0.f, ss = 0.f;
    #pragma unroll
    for (int u = 0; u < HDIM / 32; u++) {
        int idx = lane + u * 32;
        float v = hr[idx];
        sl += v * __ldg(&wl[idx]);
        sr += v * __ldg(&wr[idx]);
        ss += v * __ldg(&wsc[idx]);
    }
    #pragma unroll
    for (int o = 16; o; o >>= 1) {
        sl += __shfl_xor_sync(0xffffffffu, sl, o);
        sr += __shfl_xor_sync(0xffffffffu, sr, o);
        ss += __shfl_xor_sync(0xffffffffu, ss, o);
    }
    if (lane == 0) {
        g_yl[gw] = sl;
        g_yr[gw] = sr;
        g_sc[gw] = ss + oscb[0];
    }
}

// ========================= launch =========================
extern "C" void kernel_launch(void* const* d_in, const int* in_sizes, int n_in,
                              void* d_out, int out_size) {
    const float* x     = (const float*)d_in[0];
    const float* w_in  = (const float*)d_in[1];
    const float* b_in  = (const float*)d_in[2];
    const float* h1_wl = (const float*)d_in[3];
    const float* h1_bl = (const float*)d_in[4];
    const float* h1_wr = (const float*)d_in[5];
    const float* h2_wl = (const float*)d_in[6];
    const float* h2_bl = (const float*)d_in[7];
    const float* h2_wr = (const float*)d_in[8];
    const float* o1_wl = (const float*)d_in[9];
    const float* o1_bl = (const float*)d_in[10];
    const float* o1_wr = (const float*)d_in[11];
    const float* o2_wl = (const float*)d_in[12];
    const float* o2_bl = (const float*)d_in[13];
    const float* o2_wr = (const float*)d_in[14];
    const float* osc_w = (const float*)d_in[15];
    const float* osc_b = (const float*)d_in[16];
    float* out = (float*)d_out;

    // resolve scratch addresses
    float  *p_h0, *p_h1, *p_h2, *p_agg, *p_yl, *p_o1;
    __half *p_h0f, *p_h1f;
    cudaGetSymbolAddress((void**)&p_h0,  g_h0);
    cudaGetSymbolAddress((void**)&p_h1,  g_h1);
    cudaGetSymbolAddress((void**)&p_h2,  g_h2);
    cudaGetSymbolAddress((void**)&p_h0f, g_h0f);
    cudaGetSymbolAddress((void**)&p_h1f, g_h1f);
    cudaGetSymbolAddress((void**)&p_agg, g_agg);
    cudaGetSymbolAddress((void**)&p_yl,  g_yl);
    cudaGetSymbolAddress((void**)&p_o1,  g_o1v);

    const int SIM_SMEM = 2 * 128 * 136 * sizeof(__half);   // 69632 B dynamic
    cudaFuncSetAttribute(k_simgemm_w, cudaFuncAttributeMaxDynamicSharedMemorySize, SIM_SMEM);

    // 1) normalize (split-fp16 output)
    k_normalize<<<NN, DIN>>>(x);
    // 2) similarity matrix, upper-triangle tiles only, tensor cores (3-product split-fp16)
    dim3 gs(NTILE, NTILE);
    k_simgemm_w<<<gs, 256, SIM_SMEM>>>();
    // 3) exact quantile: 3-pass radix select; pass 1 compacts candidates (block-staged)
    k_init_sel<<<1, 256>>>();
    k_hist<0><<<1040, 256>>>();
    k_scan<<<1, 1024>>>(8192, 19);
    k_hist<1><<<1040, 256>>>();
    k_scan<<<1, 1024>>>(8192, 6);
    k_hist2c<<<1040, 256>>>();
    k_scan<<<1, 1024>>>(64, 0);
    // 4) adjacency from upper tiles (direct + bit-transposed mirror), then degrees
    k_adj_tile<<<NUT, 256>>>();
    k_deg<<<NN * 32 / 256, 256>>>();
    // 5) h0 = relu(x @ w_in + b_in)   (+ fp16 copy for aggregation)
    dim3 gd(NN / 128, HDIM / 64);
    k_sage<<<gd, 256>>>(x, w_in, DIN, nullptr, nullptr, 0, b_in, nullptr, p_h0, p_h0f, 1);
    // 6) h1 = relu(agg(h0) @ h1_wl + h1_bl + h0 @ h1_wr)
    k_agg<<<NN, 256>>>(p_h0f, p_agg);
    k_sage<<<gd, 256>>>(p_agg, h1_wl, HDIM, p_h0, h1_wr, HDIM, h1_bl, nullptr, p_h1, p_h1f, 1);
    // 7) h2 = relu(agg(h1) @ h2_wl + h2_bl + h1 @ h2_wr + h0)
    k_agg<<<NN, 256>>>(p_h1f, p_agg);
    k_sage<<<gd, 256>>>(p_agg, h2_wl, HDIM, p_h1, h2_wr, HDIM, h2_bl, p_h0, p_h2, nullptr, 1);
    // 8) output heads: agg(h2)@wl == agg(h2@wl)  (linearity) -> scalar aggregations
    k_matvec3<<<NN * 32 / 256, 256>>>(p_h2, o1_wl, o1_wr, osc_w, osc_b);
    // o1 = relu(agg1(yl) + o1_bl + yr)          (fused epilogue)
    k_agg1f<0><<<NN, 256>>>(p_yl, o1_bl, nullptr, nullptr, p_o1);
    // out = sigmoid(agg1(o1)*o2_wl + o2_bl + o1*o2_wr + sc)   (fused epilogue)
    k_agg1f<1><<<NN, 256>>>(p_o1, o2_wl, o2_bl, o2_wr, out);
}

// round 16
// speedup vs baseline: 1.3318x; 1.1659x over previous
#include <cuda_runtime.h>
#include <cuda_fp16.h>
#include <mma.h>
#include <math.h>

using namespace nvcuda;

#define NN    8192
#define DIN   128
#define HDIM  256
#define NWORD 256               // 8192/32 mask words per row
#define NTILE 64                // 8192/128 tile grid
#define NUT   2080              // upper-triangle tile count (64*65/2)
#define KRANK 63753420u         // nearest-rank index of 0.95 quantile over N*N values
#define CAND_CAP (1u << 24)     // 16M candidate slots (64 MB)

typedef unsigned long long u64;

// packed f32x2 helpers (sm_103a): 2 independent fp32 FMAs per instruction, bit-identical
#define FMA2(d, a, b)   asm("fma.rn.f32x2 %0, %1, %2, %0;" : "+l"(d) : "l"(a), "l"(b))
#define DUP2(d, s)      asm("mov.b64 %0, {%1, %1};" : "=l"(d) : "f"(s))
#define UNPK(lo, hi, s) asm("mov.b64 {%0, %1}, %2;" : "=f"(lo), "=f"(hi) : "l"(s))

// ----------------- device scratch (static globals; no runtime allocation) -----------------
__device__ __half   g_xh  [NN * DIN];          // fp16 hi part of normalized x (2 MB)
__device__ __half   g_xl  [NN * DIN];          // fp16 lo part (residual)      (2 MB)
__device__ float    g_sim [(size_t)NN * NN];   // |xn@xn^T|, UPPER TILES ONLY valid
__device__ unsigned g_adj [NN * NWORD];        // adjacency bitmask       (8 MB)
__device__ float    g_inv [NN];                // 1/deg
__device__ float    g_h0  [NN * HDIM];
__device__ float    g_h1  [NN * HDIM];
__device__ float    g_h2  [NN * HDIM];
__device__ __half   g_h0f [NN * HDIM];         // fp16 copy for aggregation
__device__ __half   g_h1f [NN * HDIM];
__device__ float    g_agg [NN * HDIM];
__device__ float    g_yl  [NN];
__device__ float    g_yr  [NN];
__device__ float    g_sc  [NN];
__device__ float    g_o1v [NN];
__device__ unsigned g_hist[8192];
__device__ unsigned g_cand[CAND_CAP];          // compacted pass-1 candidates
__device__ unsigned g_cnt;
__device__ unsigned g_key;
__device__ unsigned g_rem;

// decode linear upper-triangle tile index -> (bi, bj), bi <= bj
__device__ __forceinline__ void tile_decode(int tl, int& bi, int& bj) {
    int b = 0, rem = tl;
    while (rem >= NTILE - b) { rem -= NTILE - b; b++; }
    bi = b; bj = b + rem;
}

// ----------------- 1. row-normalize x; emit split-fp16 (hi + lo == fp32 xn) -------------
__global__ void k_normalize(const float* __restrict__ x) {
    int row = blockIdx.x;
    int t   = threadIdx.x;                 // 128 threads = 1 col each
    float v = x[row * DIN + t];
    float s = v * v;
    #pragma unroll
    for (int o = 16; o; o >>= 1) s += __shfl_xor_sync(0xffffffffu, s, o);
    __shared__ float ws[4];
    if ((t & 31) == 0) ws[t >> 5] = s;
    __syncthreads();
    float nrm = fmaxf(sqrtf(ws[0] + ws[1] + ws[2] + ws[3]), 1e-8f);
    float xn = v / nrm;
    __half hi = __float2half_rn(xn);
    __half lo = __float2half_rn(xn - __half2float(hi));
    g_xh[row * DIN + t] = hi;
    g_xl[row * DIN + t] = lo;
}

// ----------------- 2. sim = |xn @ xn^T| via tensor cores, split-fp16 3-product ----------
// Upper-triangle 128x128 tiles. Phases: (hi,hi), (lo,hi), (hi,lo); fp32 accumulate.
__global__ void __launch_bounds__(256) k_simgemm_w() {
    const int bi = blockIdx.x, bj = blockIdx.y;
    if (bj < bi) return;

    extern __shared__ __half sh2[];
    __half* Ah = sh2;                      // [128][136]
    __half* Bh = sh2 + 128 * 136;          // [128][136]

    const int t = threadIdx.x, w = t >> 5;
    const int mtp = (w & 3) * 2;           // this warp's two m-tiles
    const int nq  = (w >> 2) * 4;          // this warp's four n-tiles
    const int r0 = bi * 128, c0 = bj * 128;

    wmma::fragment<wmma::accumulator, 16, 16, 16, float> acc[2][4];
    #pragma unroll
    for (int i = 0; i < 2; i++)
        #pragma unroll
        for (int j = 0; j < 4; j++) wmma::fill_fragment(acc[i][j], 0.0f);

    #pragma unroll
    for (int phase = 0; phase < 3; phase++) {
        const __half* asrc = (phase == 1) ? g_xl : g_xh;
        const __half* bsrc = (phase == 2) ? g_xl : g_xh;
        const bool sB = (phase != 1);               // B unchanged hi->lo phase 1
        __syncthreads();
        #pragma unroll
        for (int i = 0; i < 8; i++) {
            int lin = t + i * 256;                  // 0..2047
            int r = lin >> 4, c = lin & 15;         // 16 uint4 per 128-half row
            *(uint4*)(Ah + r * 136 + c * 8) =
                *(const uint4*)(asrc + (size_t)(r0 + r) * DIN + c * 8);
            if (sB)
                *(uint4*)(Bh + r * 136 + c * 8) =
                    *(const uint4*)(bsrc + (size_t)(c0 + r) * DIN + c * 8);
        }
        __syncthreads();
        #pragma unroll
        for (int k = 0; k < 8; k++) {
            wmma::fragment<wmma::matrix_a, 16, 16, 16, __half, wmma::row_major> af[2];
            wmma::load_matrix_sync(af[0], Ah + (mtp    ) * 16 * 136 + k * 16, 136);
            wmma::load_matrix_sync(af[1], Ah + (mtp + 1) * 16 * 136 + k * 16, 136);
            #pragma unroll
            for (int j = 0; j < 4; j++) {
                wmma::fragment<wmma::matrix_b, 16, 16, 16, __half, wmma::col_major> bf;
                wmma::load_matrix_sync(bf, Bh + (nq + j) * 16 * 136 + k * 16, 136);
                wmma::mma_sync(acc[0][j], af[0], bf, acc[0][j]);
                wmma::mma_sync(acc[1][j], af[1], bf, acc[1][j]);
            }
        }
    }
    #pragma unroll
    for (int i = 0; i < 2; i++)
        #pragma unroll
        for (int j = 0; j < 4; j++) {
            #pragma unroll
            for (int e = 0; e < acc[i][j].num_elements; e++)
                acc[i][j].x[e] = fabsf(acc[i][j].x[e]);
            wmma::store_matrix_sync(
                g_sim + (size_t)(r0 + (mtp + i) * 16) * NN + c0 + (nq + j) * 16,
                acc[i][j], NN, wmma::mem_row_major);
        }
}

// ----------------- 3. exact k-th order statistic: radix select over UPPER tiles ---------
__global__ void k_init_sel() {
    if (threadIdx.x == 0) { g_key = 0u; g_rem = KRANK; g_cnt = 0u; }
    for (int i = threadIdx.x; i < 8192; i += blockDim.x) g_hist[i] = 0u;
}

template <int PASS>
__global__ void k_hist() {
    __shared__ unsigned sh[8192];
    __shared__ unsigned buf[(PASS == 1) ? 4096 : 1];
    __shared__ unsigned bcnt, gbase;
    for (int i = threadIdx.x; i < 8192; i += blockDim.x) sh[i] = 0u;
    if (threadIdx.x == 0) bcnt = 0u;
    __syncthreads();
    const unsigned key = g_key;
    const unsigned kp1 = key >> 19;
    const int t = threadIdx.x;
    for (int tl = blockIdx.x; tl < NUT; tl += gridDim.x) {
        int bi, bj; tile_decode(tl, bi, bj);
        const unsigned wgt = (bi == bj) ? 1u : 2u;
        const size_t base = (size_t)bi * 128 * NN + bj * 128;
        #pragma unroll 4
        for (int i = 0; i < 16; i++) {
            int lin = i * 256 + t;
            int r = lin >> 5, c = lin & 31;
            float4 v = __ldg((const float4*)(g_sim + base + (size_t)r * NN) + c);
            float vv[4] = {v.x, v.y, v.z, v.w};
            #pragma unroll
            for (int u = 0; u < 4; u++) {
                unsigned b = __float_as_uint(vv[u]);
                if (PASS == 0) {
                    atomicAdd(&sh[b >> 19], wgt);
                } else {
                    if ((b >> 19) == kp1) {
                        atomicAdd(&sh[(b >> 6) & 8191u], wgt);
                        unsigned slot = atomicAdd(&bcnt, wgt);   // smem atomic, rare
                        buf[slot] = b;
                        if (wgt == 2u) buf[slot + 1] = b;
                    }
                }
            }
            if (PASS == 1) {
                __syncthreads();
                if (bcnt > 2048u) {              // flush: ONE global atomic per ~2K cands
                    if (t == 0) gbase = atomicAdd(&g_cnt, bcnt);
                    __syncthreads();
                    unsigned n = bcnt, gb = gbase;
                    for (unsigned j = t; j < n; j += 256)
                        if (gb + j < CAND_CAP) g_cand[gb + j] = buf[j];
                    __syncthreads();
                    if (t == 0) bcnt = 0u;
                    __syncthreads();
                }
            }
        }
    }
    if (PASS == 1) {                              // final flush
        __syncthreads();
        if (bcnt > 0u) {
            if (t == 0) gbase = atomicAdd(&g_cnt, bcnt);
            __syncthreads();
            unsigned n = bcnt, gb = gbase;
            for (unsigned j = t; j < n; j += 256)
                if (gb + j < CAND_CAP) g_cand[gb + j] = buf[j];
        }
    }
    __syncthreads();
    for (int i = threadIdx.x; i < 8192; i += blockDim.x) {
        unsigned c = sh[i];
        if (c) atomicAdd(&g_hist[i], c);
    }
}

// pass 2: histogram bits[5:0] over compacted candidates; full-scan fallback on overflow
__global__ void k_hist2c() {
    __shared__ unsigned sh[64];
    if (threadIdx.x < 64) sh[threadIdx.x] = 0u;
    __syncthreads();
    const unsigned key = g_key;
    const unsigned kp2 = key >> 6;
    const unsigned n = g_cnt;
    if (n <= CAND_CAP) {
        for (unsigned i = blockIdx.x * blockDim.x + threadIdx.x; i < n;
             i += gridDim.x * blockDim.x) {
            unsigned b = g_cand[i];
            if ((b >> 6) == kp2) atomicAdd(&sh[b & 63u], 1u);
        }
    } else {
        const int t = threadIdx.x;
        for (int tl = blockIdx.x; tl < NUT; tl += (int)gridDim.x) {
            int bi, bj; tile_decode(tl, bi, bj);
            const unsigned wgt = (bi == bj) ? 1u : 2u;
            const size_t base = (size_t)bi * 128 * NN + bj * 128;
            #pragma unroll 4
            for (int i = 0; i < 16; i++) {
                int lin = i * 256 + t;
                int r = lin >> 5, c = lin & 31;
                float4 v = __ldg((const float4*)(g_sim + base + (size_t)r * NN) + c);
                float vv[4] = {v.x, v.y, v.z, v.w};
                #pragma unroll
                for (int u = 0; u < 4; u++) {
                    unsigned b = __float_as_uint(vv[u]);
                    if ((b >> 6) == kp2) atomicAdd(&sh[b & 63u], wgt);
                }
            }
        }
    }
    __syncthreads();
    if (threadIdx.x < 64) {
        unsigned c = sh[threadIdx.x];
        if (c) atomicAdd(&g_hist[threadIdx.x], c);
    }
}

// parallel-prefix scan: 1024 threads, shfl warp-scan + 32-word combine
__global__ void __launch_bounds__(1024) k_scan(int nbins, int shift) {
    __shared__ unsigned s[8192];
    __shared__ unsigned wsum[32];
    int t = threadIdx.x;                    // 1024 threads, single block
    for (int i = t; i < nbins; i += 1024) s[i] = g_hist[i];
    __syncthreads();
    int per = (nbins + 1023) / 1024;
    int lo = t * per; if (lo > nbins) lo = nbins;
    int hi = lo + per; if (hi > nbins) hi = nbins;
    unsigned mysum = 0;
    for (int i = lo; i < hi; i++) mysum += s[i];
    unsigned inc = mysum;
    #pragma unroll
    for (int o = 1; o < 32; o <<= 1) {
        unsigned v = __shfl_up_sync(0xffffffffu, inc, o);
        if ((t & 31) >= o) inc += v;
    }
    if ((t & 31) == 31) wsum[t >> 5] = inc;
    __syncthreads();
    unsigned wpre = 0;
    #pragma unroll
    for (int i = 0; i < 32; i++) if (i < (t >> 5)) wpre += wsum[i];
    unsigned pre = wpre + inc - mysum;      // exclusive prefix for this thread
    unsigned rem = g_rem;
    __syncthreads();                        // all read g_rem before the winner writes it
    if (mysum > 0 && rem >= pre && rem < pre + mysum) {
        unsigned r = rem - pre;
        for (int i = lo; i < hi; i++) {
            if (r < s[i]) { g_key |= ((unsigned)i) << shift; g_rem = r; break; }
            r -= s[i];
        }
    }
    __syncthreads();
    for (int i = t; i < nbins; i += 1024) g_hist[i] = 0u;  // ready for next pass / replay
}

// ----------------- 4. adjacency from upper tiles: direct + bit-transposed mirror --------
__global__ void __launch_bounds__(256) k_adj_tile() {
    __shared__ unsigned bits[128][4];
    int bi, bj; tile_decode(blockIdx.x, bi, bj);
    const int t = threadIdx.x, lane = t & 31, w = t >> 5;   // 8 warps
    const float eps = __uint_as_float(g_key);
    const int r0 = bi * 128, c0 = bj * 128;
    const int cw0 = c0 >> 5, rw0 = r0 >> 5;

    #pragma unroll
    for (int rr = 0; rr < 16; rr++) {
        int r = w * 16 + rr;
        const float* srow = g_sim + (size_t)(r0 + r) * NN + c0;
        #pragma unroll
        for (int q = 0; q < 4; q++) {
            float v = srow[q * 32 + lane];
            unsigned m = __ballot_sync(0xffffffffu, v >= eps);
            if (lane == 0) {
                g_adj[(r0 + r) * NWORD + cw0 + q] = m;
                bits[r][q] = m;
            }
        }
    }
    if (bi == bj) return;
    __syncthreads();

    const int qr = w >> 1;                  // warps 0..7 -> qr 0..3
    const int chalf = (w & 1) * 64;         // c range [chalf, chalf+64)
    unsigned wa = bits[qr * 32 + lane][(chalf >> 5) + 0];
    unsigned wb = bits[qr * 32 + lane][(chalf >> 5) + 1];
    #pragma unroll
    for (int cc = 0; cc < 32; cc++) {
        unsigned m = __ballot_sync(0xffffffffu, (wa >> cc) & 1u);
        if (lane == 0) g_adj[(c0 + chalf + cc) * NWORD + rw0 + qr] = m;
    }
    #pragma unroll
    for (int cc = 0; cc < 32; cc++) {
        unsigned m = __ballot_sync(0xffffffffu, (wb >> cc) & 1u);
        if (lane == 0) g_adj[(c0 + chalf + 32 + cc) * NWORD + rw0 + qr] = m;
    }
}

// ----------------- 4b. degrees: popc over adjacency rows -----------------
__global__ void k_deg() {
    int row  = (blockIdx.x * blockDim.x + threadIdx.x) >> 5;  // one warp / row
    int lane = threadIdx.x & 31;
    if (row >= NN) return;
    const unsigned* ar = g_adj + row * NWORD;
    int cnt = 0;
    #pragma unroll
    for (int i = 0; i < 8; i++) cnt += __popc(ar[lane + i * 32]);
    #pragma unroll
    for (int o = 16; o; o >>= 1) cnt += __shfl_xor_sync(0xffffffffu, cnt, o);
    if (lane == 0) g_inv[row] = 1.0f / fmaxf((float)cnt, 1.0f);
}

// ----------------- 5. fused dense / SAGE GEMM, FFMA2 inner ------------------------------
__global__ void __launch_bounds__(256) k_sage(
    const float* __restrict__ A1, const float* __restrict__ W1, int K1,
    const float* __restrict__ A2, const float* __restrict__ W2, int K2,
    const float* __restrict__ bias, const float* __restrict__ res,
    float* __restrict__ out, __half* __restrict__ out16, int relu)
{
    __shared__ float As[16][132];
    __shared__ float Bs[16][68];
    const int t  = threadIdx.x;
    const int tx = t & 15, ty = t >> 4;
    const int r0 = blockIdx.x * 128, c0 = blockIdx.y * 64;

    u64 acc2[8][2];
    #pragma unroll
    for (int i = 0; i < 8; i++) { acc2[i][0] = 0ull; acc2[i][1] = 0ull; }

    const float* Ap = A1; const float* Wp = W1; int K = K1;
    for (int phase = 0; phase < 2; phase++) {
        if (phase == 1) {
            if (A2 == nullptr) break;
            Ap = A2; Wp = W2; K = K2;
        }
        for (int k0 = 0; k0 < K; k0 += 16) {
            #pragma unroll
            for (int i = 0; i < 2; i++) {
                int lid = t + i * 256;
                int row = lid >> 2;             // 0..127
                int q   = lid & 3;
                float4 a = *(const float4*)(Ap + (size_t)(r0 + row) * K + k0 + q * 4);
                As[q*4+0][row] = a.x; As[q*4+1][row] = a.y;
                As[q*4+2][row] = a.z; As[q*4+3][row] = a.w;
            }
            {
                int kk = t >> 4, n4 = (t & 15) * 4;
                float4 b = *(const float4*)(Wp + (size_t)(k0 + kk) * HDIM + c0 + n4);
                Bs[kk][n4+0] = b.x; Bs[kk][n4+1] = b.y;
                Bs[kk][n4+2] = b.z; Bs[kk][n4+3] = b.w;
            }
            __syncthreads();
            #pragma unroll
            for (int kk = 0; kk < 16; kk++) {
                float a[8];
                *(float4*)&a[0] = *(const float4*)&As[kk][ty * 4];
                *(float4*)&a[4] = *(const float4*)&As[kk][64 + ty * 4];
                u64 bv[2];
                {
                    const u64* bp = (const u64*)&Bs[kk][tx * 4];
                    bv[0] = bp[0]; bv[1] = bp[1];
                }
                #pragma unroll
                for (int i = 0; i < 8; i++) {
                    u64 a2; DUP2(a2, a[i]);
                    FMA2(acc2[i][0], a2, bv[0]);
                    FMA2(acc2[i][1], a2, bv[1]);
                }
            }
            __syncthreads();
        }
    }
    float bvv[4];
    *(float4*)bvv = *(const float4*)(bias + c0 + tx * 4);
    #pragma unroll
    for (int i = 0; i < 8; i++) {
        int row = r0 + ((i >> 2) << 6) + ty * 4 + (i & 3);
        float v[4];
        UNPK(v[0], v[1], acc2[i][0]);
        UNPK(v[2], v[3], acc2[i][1]);
        #pragma unroll
        for (int j = 0; j < 4; j++) v[j] += bvv[j];
        if (res) {
            float4 rr = *(const float4*)(res + (size_t)row * HDIM + c0 + tx * 4);
            v[0] += rr.x; v[1] += rr.y; v[2] += rr.z; v[3] += rr.w;
        }
        if (relu) {
            #pragma unroll
            for (int j = 0; j < 4; j++) v[j] = fmaxf(v[j], 0.f);
        }
        *(float4*)(out + (size_t)row * HDIM + c0 + tx * 4) = make_float4(v[0], v[1], v[2], v[3]);
        if (out16) {
            __half2 h01 = __floats2half2_rn(v[0], v[1]);
            __half2 h23 = __floats2half2_rn(v[2], v[3]);
            uint2 pk;
            pk.x = *(unsigned*)&h01;
            pk.y = *(unsigned*)&h23;
            *(uint2*)(out16 + (size_t)row * HDIM + c0 + tx * 4) = pk;
        }
    }
}

// ----------------- 6. mean aggregation, width 256: 8 warp-groups, uint4 loads -----------
// Each warp scans 32 mask words (~51 edges, half the old serial chain); each lane covers
// 8 columns via ONE uint4 (16B) load per edge (was 2x uint2). fp32 accumulate.
__global__ void __launch_bounds__(256) k_agg(const __half* __restrict__ h, float* __restrict__ out) {
    __shared__ unsigned sm[NWORD];
    __shared__ float red[8][HDIM];
    int row  = blockIdx.x;
    int t    = threadIdx.x;
    int g    = t >> 5;                      // warp-group 0..7 (32 mask words each)
    int lane = t & 31;                      // cols [lane*8, lane*8+8)
    sm[t] = g_adj[row * NWORD + t];
    __syncthreads();
    float acc[8];
    #pragma unroll
    for (int j = 0; j < 8; j++) acc[j] = 0.f;
    const __half* hc = h + lane * 8;
    for (int w = g * 32; w < g * 32 + 32; w++) {
        unsigned m = sm[w];
        int base = w << 5;
        while (m) {
            int b0 = __ffs(m) - 1; m &= m - 1;
            uint4 v0 = __ldg((const uint4*)(hc + ((size_t)(base + b0) << 8)));
            if (m) {
                int b1 = __ffs(m) - 1; m &= m - 1;
                uint4 v1 = __ldg((const uint4*)(hc + ((size_t)(base + b1) << 8)));
                float2 p0 = __half22float2(*(__half2*)&v0.x), q0 = __half22float2(*(__half2*)&v1.x);
                float2 p1 = __half22float2(*(__half2*)&v0.y), q1 = __half22float2(*(__half2*)&v1.y);
                float2 p2 = __half22float2(*(__half2*)&v0.z), q2 = __half22float2(*(__half2*)&v1.z);
                float2 p3 = __half22float2(*(__half2*)&v0.w), q3 = __half22float2(*(__half2*)&v1.w);
                acc[0] += p0.x + q0.x; acc[1] += p0.y + q0.y;
                acc[2] += p1.x + q1.x; acc[3] += p1.y + q1.y;
                acc[4] += p2.x + q2.x; acc[5] += p2.y + q2.y;
                acc[6] += p3.x + q3.x; acc[7] += p3.y + q3.y;
            } else {
                float2 p0 = __half22float2(*(__half2*)&v0.x);
                float2 p1 = __half22float2(*(__half2*)&v0.y);
                float2 p2 = __half22float2(*(__half2*)&v0.z);
                float2 p3 = __half22float2(*(__half2*)&v0.w);
                acc[0] += p0.x; acc[1] += p0.y;
                acc[2] += p1.x; acc[3] += p1.y;
                acc[4] += p2.x; acc[5] += p2.y;
                acc[6] += p3.x; acc[7] += p3.y;
            }
        }
    }
    #pragma unroll
    for (int j = 0; j < 2; j++)
        *(float4*)(&red[g][lane * 8 + j * 4]) = *(float4*)(&acc[j * 4]);
    __syncthreads();
    if (t < 64) {
        float4 r = make_float4(0.f, 0.f, 0.f, 0.f);
        #pragma unroll
        for (int gg = 0; gg < 8; gg++) {
            float4 a = ((float4*)red[gg])[t];
            r.x += a.x; r.y += a.y; r.z += a.z; r.w += a.w;
        }
        float inv = g_inv[row];
        r.x *= inv; r.y *= inv; r.z *= inv; r.w *= inv;
        ((float4*)(out + ((size_t)row << 8)))[t] = r;
    }
}

// ----------------- 7. width-1 aggregation with fused epilogues -----------------
// mode 0: out[row] = relu(agg1(y)[row] + w0 + g_yr[row])
// mode 1: out[row] = sigmoid(agg1(y)[row]*w0 + w1 + y[row]*w2 + g_sc[row])
template <int MODE>
__global__ void __launch_bounds__(256) k_agg1f(const float* __restrict__ y,
                                               const float* __restrict__ w0,
                                               const float* __restrict__ w1,
                                               const float* __restrict__ w2,
                                               float* __restrict__ out) {
    __shared__ float sred[8];
    int row = blockIdx.x, t = threadIdx.x;
    unsigned m = g_adj[row * NWORD + t];
    int base = t << 5;
    float acc = 0.f;
    while (m) {
        int b = __ffs(m) - 1;
        m &= m - 1;
        acc += __ldg(&y[base + b]);
    }
    #pragma unroll
    for (int o = 16; o; o >>= 1) acc += __shfl_xor_sync(0xffffffffu, acc, o);
    if ((t & 31) == 0) sred[t >> 5] = acc;
    __syncthreads();
    if (t == 0) {
        float v = 0.f;
        #pragma unroll
        for (int i = 0; i < 8; i++) v += sred[i];
        float a = v * g_inv[row];
        if (MODE == 0) {
            out[row] = fmaxf(a + w0[0] + g_yr[row], 0.f);
        } else {
            float o = a * w0[0] + w1[0] + y[row] * w2[0] + g_sc[row];
            out[row] = 1.0f / (1.0f + expf(-o));
        }
    }
}

// ----------------- 8. three fused matvecs -----------------
__global__ void k_matvec3(const float* __restrict__ h,
                          const float* __restrict__ wl, const float* __restrict__ wr,
                          const float* __restrict__ wsc, const float* __restrict__ oscb) {
    int gw   = (blockIdx.x * blockDim.x + threadIdx.x) >> 5;   // one warp per row
    int lane = threadIdx.x & 31;
    if (gw >= NN) return;
    const float* hr = h + (size_t)gw * HDIM;
    float sl = 0.f, sr = 0.f, ss = 0.f;
    #pragma unroll
    for (int u = 0; u < HDIM / 32; u++) {
        int idx = lane + u * 32;
        float v = hr[idx];
        sl += v * __ldg(&wl[idx]);
        sr += v * __ldg(&wr[idx]);
        ss += v * __ldg(&wsc[idx]);
    }
    #pragma unroll
    for (int o = 16; o; o >>= 1) {
        sl += __shfl_xor_sync(0xffffffffu, sl, o);
        sr += __shfl_xor_sync(0xffffffffu, sr, o);
        ss += __shfl_xor_sync(0xffffffffu, ss, o);
    }
    if (lane == 0) {
        g_yl[gw] = sl;
        g_yr[gw] = sr;
        g_sc[gw] = ss + oscb[0];
    }
}

// ========================= launch =========================
extern "C" void kernel_launch(void* const* d_in, const int* in_sizes, int n_in,
                              void* d_out, int out_size) {
    const float* x     = (const float*)d_in[0];
    const float* w_in  = (const float*)d_in[1];
    const float* b_in  = (const float*)d_in[2];
    const float* h1_wl = (const float*)d_in[3];
    const float* h1_bl = (const float*)d_in[4];
    const float* h1_wr = (const float*)d_in[5];
    const float* h2_wl = (const float*)d_in[6];
    const float* h2_bl = (const float*)d_in[7];
    const float* h2_wr = (const float*)d_in[8];
    const float* o1_wl = (const float*)d_in[9];
    const float* o1_bl = (const float*)d_in[10];
    const float* o1_wr = (const float*)d_in[11];
    const float* o2_wl = (const float*)d_in[12];
    const float* o2_bl = (const float*)d_in[13];
    const float* o2_wr = (const float*)d_in[14];
    const float* osc_w = (const float*)d_in[15];
    const float* osc_b = (const float*)d_in[16];
    float* out = (float*)d_out;

    // resolve scratch addresses
    float  *p_h0, *p_h1, *p_h2, *p_agg, *p_yl, *p_o1;
    __half *p_h0f, *p_h1f;
    cudaGetSymbolAddress((void**)&p_h0,  g_h0);
    cudaGetSymbolAddress((void**)&p_h1,  g_h1);
    cudaGetSymbolAddress((void**)&p_h2,  g_h2);
    cudaGetSymbolAddress((void**)&p_h0f, g_h0f);
    cudaGetSymbolAddress((void**)&p_h1f, g_h1f);
    cudaGetSymbolAddress((void**)&p_agg, g_agg);
    cudaGetSymbolAddress((void**)&p_yl,  g_yl);
    cudaGetSymbolAddress((void**)&p_o1,  g_o1v);

    const int SIM_SMEM = 2 * 128 * 136 * sizeof(__half);   // 69632 B dynamic
    cudaFuncSetAttribute(k_simgemm_w, cudaFuncAttributeMaxDynamicSharedMemorySize, SIM_SMEM);

    // 1) normalize (split-fp16 output)
    k_normalize<<<NN, DIN>>>(x);
    // 2) similarity matrix, upper-triangle tiles only, tensor cores (3-product split-fp16)
    dim3 gs(NTILE, NTILE);
    k_simgemm_w<<<gs, 256, SIM_SMEM>>>();
    // 3) exact quantile: 3-pass radix select; pass 1 compacts candidates (block-staged)
    k_init_sel<<<1, 256>>>();
    k_hist<0><<<1040, 256>>>();
    k_scan<<<1, 1024>>>(8192, 19);
    k_hist<1><<<1040, 256>>>();
    k_scan<<<1, 1024>>>(8192, 6);
    k_hist2c<<<1040, 256>>>();
    k_scan<<<1, 1024>>>(64, 0);
    // 4) adjacency from upper tiles (direct + bit-transposed mirror), then degrees
    k_adj_tile<<<NUT, 256>>>();
    k_deg<<<NN * 32 / 256, 256>>>();
    // 5) h0 = relu(x @ w_in + b_in)   (+ fp16 copy for aggregation)
    dim3 gd(NN / 128, HDIM / 64);
    k_sage<<<gd, 256>>>(x, w_in, DIN, nullptr, nullptr, 0, b_in, nullptr, p_h0, p_h0f, 1);
    // 6) h1 = relu(agg(h0) @ h1_wl + h1_bl + h0 @ h1_wr)
    k_agg<<<NN, 256>>>(p_h0f, p_agg);
    k_sage<<<gd, 256>>>(p_agg, h1_wl, HDIM, p_h0, h1_wr, HDIM, h1_bl, nullptr, p_h1, p_h1f, 1);
    // 7) h2 = relu(agg(h1) @ h2_wl + h2_bl + h1 @ h2_wr + h0)
    k_agg<<<NN, 256>>>(p_h1f, p_agg);
    k_sage<<<gd, 256>>>(p_agg, h2_wl, HDIM, p_h1, h2_wr, HDIM, h2_bl, p_h0, p_h2, nullptr, 1);
    // 8) output heads: agg(h2)@wl == agg(h2@wl)  (linearity) -> scalar aggregations
    k_matvec3<<<NN * 32 / 256, 256>>>(p_h2, o1_wl, o1_wr, osc_w, osc_b);
    // o1 = relu(agg1(yl) + o1_bl + yr)          (fused epilogue)
    k_agg1f<0><<<NN, 256>>>(p_yl, o1_bl, nullptr, nullptr, p_o1);
    // out = sigmoid(agg1(o1)*o2_wl + o2_bl + o1*o2_wr + sc)   (fused epilogue)
    k_agg1f<1><<<NN, 256>>>(p_o1, o2_wl, o2_bl, o2_wr, out);
}